// round 12
// baseline (speedup 1.0000x reference)
#include <cuda_runtime.h>
#include <cstdint>

// p-bit Glauber, N=4096, 16384 steps. Segment-restart architecture:
//  prep_misc : thr=atanh(2u-1)+idx zip, g_idx, g_m=sign(m0)
//  pack_T    : per segment s, T[t'][t] = J[idx(t')][idx(t)] (2048x2048, 16MB x8)
//  init_F    : g_F = J@m0 + h (full grid)
//  seq_seg(s): single CTA, 544 thr. 512 G-keepers hold G[t]=F[idx(t)] for all
//              2048 segment steps in registers; per flip they add d*T[t'][t]
//              for future steps only (coalesced float4, ~4KB/flip avg).
//              Evaluator warp = R10 logic (Tw in-window, Tc 1-window catch-up,
//              both staged slices of T). One __syncthreads per window.
//  fold_flips(s): full-grid g_F += sum d*J[i_k,:] over segment-s flips
//              (13MB from L2 across all SMs) -> next segment's G init.

#define NN      4096
#define NSTEPS  16384
#define W       64
#define SS      2048
#define WPS     (SS / W)        // 32
#define NSEG    (NSTEPS / SS)   // 8
#define TPB     544
#define FULLM   0xffffffffu

__device__ float       g_F[NN];
__device__ float2      g_TI[NSTEPS];
__device__ int         g_idx[NSTEPS];
__device__ signed char g_m[NN];
__device__ int         g_fl[NSTEPS];        // per-seg flip records: spin | sign<<30
__device__ int         g_flipCnt[NSEG];
__device__ float       g_T[(size_t)NSEG * SS * SS];   // 134MB

struct Sm {
    float Tw[2][W * W];     // 32KB
    float Tc[2][W * W];     // 32KB
    float Gpub[2][W];
    int   flist[2][W];      // local step | sign<<30
    int   fcnt[2];
    signed char m[NN];      // 4KB
};
#define SMEM_BYTES ((int)sizeof(Sm))

// ---------------------------------------------------------------------------
__global__ void prep_misc(const int* __restrict__ idx,
                          const float* __restrict__ u,
                          const float* __restrict__ m0) {
    const int bid = blockIdx.x;
    if (bid < NSTEPS / 256) {
        const int t = bid * 256 + threadIdx.x;
        const float r = 2.0f * u[t] - 1.0f;
        g_TI[t]  = make_float2(atanhf(r), __int_as_float(idx[t]));
        g_idx[t] = idx[t];
    } else {
        const int k = (bid - NSTEPS / 256) * 256 + threadIdx.x;
        g_m[k] = (m0[k] > 0.0f) ? 1 : -1;
    }
}

// ---------------------------------------------------------------------------
__global__ void pack_T(const float* __restrict__ J) {
    __shared__ float rowS[NN];      // 16KB
    __shared__ int   ids[SS];       // 8KB
    const int tglob = blockIdx.x;            // global step t'
    const int s  = tglob / SS;
    const int tp = tglob % SS;
    const int rowIdx = g_idx[tglob];

    const float4* __restrict__ Jr =
        reinterpret_cast<const float4*>(J) + (size_t)rowIdx * (NN / 4);
    for (int k = threadIdx.x; k < NN / 4; k += 256)
        reinterpret_cast<float4*>(rowS)[k] = Jr[k];
    for (int k = threadIdx.x; k < SS; k += 256)
        ids[k] = g_idx[s * SS + k];
    __syncthreads();

    float* __restrict__ dst = g_T + (size_t)s * SS * SS + (size_t)tp * SS;
    const int base = threadIdx.x * 8;
    #pragma unroll
    for (int j = 0; j < 8; j++)
        dst[base + j] = rowS[ids[base + j]];
}

// ---------------------------------------------------------------------------
__global__ void init_F(const float* __restrict__ J,
                       const float* __restrict__ h,
                       const float* __restrict__ m0) {
    const int row = blockIdx.x;
    const float4* __restrict__ Jr =
        reinterpret_cast<const float4*>(J) + (size_t)row * (NN / 4);
    const float4* __restrict__ M4 = reinterpret_cast<const float4*>(m0);
    float sum = 0.0f;
    for (int k = threadIdx.x; k < NN / 4; k += blockDim.x) {
        float4 a = Jr[k];
        float4 b = M4[k];
        sum += a.x * b.x + a.y * b.y + a.z * b.z + a.w * b.w;
    }
    #pragma unroll
    for (int off = 16; off; off >>= 1)
        sum += __shfl_xor_sync(FULLM, sum, off);
    __shared__ float ws[8];
    const int lane = threadIdx.x & 31;
    const int wid  = threadIdx.x >> 5;
    if (lane == 0) ws[wid] = sum;
    __syncthreads();
    if (threadIdx.x == 0) {
        float tot = 0.0f;
        #pragma unroll
        for (int w = 0; w < 8; w++) tot += ws[w];
        g_F[row] = tot + h[row];
    }
}

// ---------------------------------------------------------------------------
__global__ void fold_flips(const float* __restrict__ J, int s) {
    const int col = blockIdx.x * blockDim.x + threadIdx.x;   // 16 x 256 = 4096
    const int n = g_flipCnt[s];
    const int* __restrict__ fl = g_fl + s * SS;
    float f = g_F[col];
    int k = 0;
    for (; k + 8 <= n; k += 8) {
        float v[8], d[8];
        #pragma unroll
        for (int j = 0; j < 8; j++) {
            const int e = fl[k + j];
            d[j] = (e & (1 << 30)) ? 2.0f : -2.0f;
            v[j] = __ldg(J + (size_t)(e & 0xFFFF) * NN + col);
        }
        #pragma unroll
        for (int j = 0; j < 8; j++)
            f = fmaf(v[j], d[j], f);
    }
    for (; k < n; k++) {
        const int e = fl[k];
        const float d = (e & (1 << 30)) ? 2.0f : -2.0f;
        f = fmaf(__ldg(J + (size_t)(e & 0xFFFF) * NN + col), d, f);
    }
    g_F[col] = f;
}

// ---------------------------------------------------------------------------
__global__ __launch_bounds__(TPB, 1)
void seq_seg(float* __restrict__ out, int s) {
    extern __shared__ char raw[];
    Sm* S = reinterpret_cast<Sm*>(raw);

    const int tid  = threadIdx.x;
    const int lane = tid & 31;
    const bool is_ev = (tid < 32);
    const int kid   = tid - 32;            // keeper id [0,512)
    const int tbase = 4 * kid;             // owned local steps tbase..tbase+3
    const int segBase = s * SS;
    const float* __restrict__ Tseg = g_T + (size_t)s * SS * SS;

    // ---- prologue ----
    for (int k = tid; k < NN; k += TPB)
        S->m[k] = g_m[k];
    if (tid == 0) { S->fcnt[0] = 0; S->fcnt[1] = 0; }

    float4 Greg = make_float4(0.f, 0.f, 0.f, 0.f);
    float2 tiPF0 = make_float2(0.f, 0.f), tiPF1 = tiPF0;
    unsigned prevM0 = 0, prevS0 = 0, prevM1 = 0, prevS1 = 0;
    int gtot = 0;

    if (is_ev) {
        tiPF0 = g_TI[segBase + lane];
        tiPF1 = g_TI[segBase + 32 + lane];
    } else {
        // G init from g_F at the 4 owned step indices
        const float2 a = g_TI[segBase + tbase];
        const float2 b = g_TI[segBase + tbase + 1];
        const float2 c = g_TI[segBase + tbase + 2];
        const float2 d = g_TI[segBase + tbase + 3];
        Greg.x = g_F[__float_as_int(a.y)];
        Greg.y = g_F[__float_as_int(b.y)];
        Greg.z = g_F[__float_as_int(c.y)];
        Greg.w = g_F[__float_as_int(d.y)];
        // stage Tw[0] (window 0 x window 0)
        const int krow  = kid >> 3;
        const int lbase = (kid & 7) * 8;
        const float* wsrc = Tseg + (size_t)krow * SS + lbase;
        float4 wa = *reinterpret_cast<const float4*>(wsrc);
        float4 wb = *reinterpret_cast<const float4*>(wsrc + 4);
        *reinterpret_cast<float4*>(&S->Tw[0][krow * W + lbase])     = wa;
        *reinterpret_cast<float4*>(&S->Tw[0][krow * W + lbase + 4]) = wb;
        if (kid < 16)
            *reinterpret_cast<float4*>(&S->Gpub[0][tbase]) = Greg;
    }
    __syncthreads();

    // ---- main loop over windows ----
    for (int p = 0; p < WPS; p++) {
        const int par = p & 1;
        if (is_ev) {
            const float thr0 = tiPF0.x;
            const int   i0   = __float_as_int(tiPF0.y);
            const float thr1 = tiPF1.x;
            const int   i1x  = __float_as_int(tiPF1.y);
            float f0  = S->Gpub[par][lane];
            float f1v = S->Gpub[par][32 + lane];
            bool pos0 = (S->m[i0]  > 0);
            bool pos1 = (S->m[i1x] > 0);
            if (p + 1 < WPS) {
                tiPF0 = g_TI[segBase + (p + 1) * W + lane];
                tiPF1 = g_TI[segBase + (p + 1) * W + 32 + lane];
            }

            // catch up window p-1's flips
            const float* TcP = S->Tc[par];
            {
                unsigned mm = prevM0;
                while (mm) {
                    const int k = __ffs(mm) - 1;
                    mm &= mm - 1;
                    const float dk = ((prevS0 >> k) & 1u) ? 2.0f : -2.0f;
                    f0  = fmaf(TcP[(k << 6) + lane],      dk, f0);
                    f1v = fmaf(TcP[(k << 6) + 32 + lane], dk, f1v);
                }
                mm = prevM1;
                while (mm) {
                    const int k = __ffs(mm) - 1;
                    mm &= mm - 1;
                    const int r = 32 + k;
                    const float dk = ((prevS1 >> k) & 1u) ? 2.0f : -2.0f;
                    f0  = fmaf(TcP[(r << 6) + lane],      dk, f0);
                    f1v = fmaf(TcP[(r << 6) + 32 + lane], dk, f1v);
                }
            }

            const float* TwP = S->Tw[par];
            unsigned nM0 = 0, nS0 = 0, nM1 = 0, nS1 = 0;
            int cnt = 0;

            // half A (steps 0..31 of window)
            {
                bool sp = (f0 >= thr0);
                bool fl = sp != pos0;
                unsigned fb  = __ballot_sync(FULLM, fl);
                unsigned sbm = __ballot_sync(FULLM, sp);
                while (fb) {
                    const int  f = __ffs(fb) - 1;
                    const bool s1 = (sbm >> f) & 1u;
                    const float d = s1 ? 2.0f : -2.0f;
                    const float jva = TwP[(f << 6) + lane];
                    const float jvb = TwP[(f << 6) + 32 + lane];
                    const int   ii  = __shfl_sync(FULLM, i0, f);
                    if (lane == f) {
                        S->m[ii] = s1 ? 1 : -1;
                        const int sg = s1 ? (1 << 30) : 0;
                        S->flist[par][cnt] = (p * W + f) | sg;
                        g_fl[segBase + gtot + cnt] = ii | sg;
                    }
                    nM0 |= 1u << f;
                    if (s1) nS0 |= 1u << f;
                    cnt++;
                    f0  = fmaf(jva, d, f0);
                    f1v = fmaf(jvb, d, f1v);
                    if (i0  == ii) pos0 = s1;
                    if (i1x == ii) pos1 = s1;
                    bool ns = false, nf2 = false;
                    if (lane > f) {
                        ns  = (f0 >= thr0);
                        nf2 = ns != pos0;
                    }
                    fb  = __ballot_sync(FULLM, nf2);
                    sbm = __ballot_sync(FULLM, ns);
                }
            }
            // half B (steps 32..63)
            {
                bool sp = (f1v >= thr1);
                bool fl = sp != pos1;
                unsigned fb  = __ballot_sync(FULLM, fl);
                unsigned sbm = __ballot_sync(FULLM, sp);
                while (fb) {
                    const int  f = __ffs(fb) - 1;
                    const bool s1 = (sbm >> f) & 1u;
                    const float d = s1 ? 2.0f : -2.0f;
                    const int  r = 32 + f;
                    const float jvb = TwP[(r << 6) + 32 + lane];
                    const int   ii  = __shfl_sync(FULLM, i1x, f);
                    if (lane == f) {
                        S->m[ii] = s1 ? 1 : -1;
                        const int sg = s1 ? (1 << 30) : 0;
                        S->flist[par][cnt] = (p * W + 32 + f) | sg;
                        g_fl[segBase + gtot + cnt] = ii | sg;
                    }
                    nM1 |= 1u << f;
                    if (s1) nS1 |= 1u << f;
                    cnt++;
                    f1v = fmaf(jvb, d, f1v);
                    if (i1x == ii) pos1 = s1;
                    bool ns = false, nf2 = false;
                    if (lane > f) {
                        ns  = (f1v >= thr1);
                        nf2 = ns != pos1;
                    }
                    fb  = __ballot_sync(FULLM, nf2);
                    sbm = __ballot_sync(FULLM, ns);
                }
            }
            if (lane == 0) S->fcnt[par] = cnt;
            gtot += cnt;
            prevM0 = nM0; prevS0 = nS0;
            prevM1 = nM1; prevS1 = nS1;
        } else {
            // ================= keepers =================
            const bool hasNext = (p + 1 < WPS);
            const int krow  = kid >> 3;
            const int lbase = (kid & 7) * 8;
            float4 wa, wb, ca, cb;
            if (hasNext) {   // stage tables for window p+1 (issue LDGs early)
                const float* wsrc =
                    Tseg + (size_t)((p + 1) * W + krow) * SS + (p + 1) * W + lbase;
                const float* csrc =
                    Tseg + (size_t)(p * W + krow) * SS + (p + 1) * W + lbase;
                wa = *reinterpret_cast<const float4*>(wsrc);
                wb = *reinterpret_cast<const float4*>(wsrc + 4);
                ca = *reinterpret_cast<const float4*>(csrc);
                cb = *reinterpret_cast<const float4*>(csrc + 4);
            }

            // apply window p-1's flips to future-owned G
            const int np = S->fcnt[par ^ 1];
            const int* fl = S->flist[par ^ 1];
            const bool active = (tbase >= (p + 1) * W);
            const float* rowBase = Tseg + tbase;
            for (int kb = 0; kb < np; kb += 4) {
                float  dd[4];
                float4 v[4];
                #pragma unroll
                for (int j = 0; j < 4; j++) {
                    const bool vld = (kb + j < np);
                    const int e = vld ? fl[kb + j] : 0;
                    dd[j] = vld ? ((e & (1 << 30)) ? 2.0f : -2.0f) : 0.0f;
                    const int tp2 = e & 0xFFFF;
                    v[j] = (vld && active)
                        ? *reinterpret_cast<const float4*>(rowBase + (size_t)tp2 * SS)
                        : make_float4(0.f, 0.f, 0.f, 0.f);
                }
                #pragma unroll
                for (int j = 0; j < 4; j++) {
                    Greg.x = fmaf(v[j].x, dd[j], Greg.x);
                    Greg.y = fmaf(v[j].y, dd[j], Greg.y);
                    Greg.z = fmaf(v[j].z, dd[j], Greg.z);
                    Greg.w = fmaf(v[j].w, dd[j], Greg.w);
                }
            }

            if (hasNext) {
                *reinterpret_cast<float4*>(&S->Tw[par ^ 1][krow * W + lbase])     = wa;
                *reinterpret_cast<float4*>(&S->Tw[par ^ 1][krow * W + lbase + 4]) = wb;
                *reinterpret_cast<float4*>(&S->Tc[par ^ 1][krow * W + lbase])     = ca;
                *reinterpret_cast<float4*>(&S->Tc[par ^ 1][krow * W + lbase + 4]) = cb;
                if ((kid >> 4) == (p + 1))     // publish G for window p+1
                    *reinterpret_cast<float4*>(&S->Gpub[par ^ 1][tbase - (p + 1) * W]) = Greg;
            }
        }
        __syncthreads();
    }

    // ---- epilogue ----
    for (int k = tid; k < NN; k += TPB)
        g_m[k] = S->m[k];
    if (is_ev && lane == 0)
        g_flipCnt[s] = gtot;
    if (s == NSEG - 1)
        for (int k = tid; k < NN; k += TPB)
            out[k] = (float)S->m[k];
}

// ---------------------------------------------------------------------------
extern "C" void kernel_launch(void* const* d_in, const int* in_sizes, int n_in,
                              void* d_out, int out_size) {
    const float* J  = (const float*)d_in[0];
    const float* h  = (const float*)d_in[1];
    const float* m0 = (const float*)d_in[2];
    const int*   idx= (const int*)  d_in[3];
    const float* u  = (const float*)d_in[4];
    float* out = (float*)d_out;

    static bool attrSet = false;
    if (!attrSet) {
        cudaFuncSetAttribute(seq_seg,
                             cudaFuncAttributeMaxDynamicSharedMemorySize,
                             SMEM_BYTES);
        attrSet = true;
    }

    prep_misc<<<NSTEPS / 256 + NN / 256, 256>>>(idx, u, m0);
    pack_T<<<NSEG * SS, 256>>>(J);
    init_F<<<NN, 256>>>(J, h, m0);
    for (int s = 0; s < NSEG; s++) {
        seq_seg<<<1, TPB, SMEM_BYTES>>>(out, s);
        if (s + 1 < NSEG)
            fold_flips<<<NN / 256, 256>>>(J, s);
    }
}

// round 13
// speedup vs baseline: 1.2137x; 1.2137x over previous
#include <cuda_runtime.h>
#include <cstdint>

// p-bit Glauber, N=4096, 16384 steps. Segment-restart architecture, v2:
//  SS=1024 (16 segments) so the step-pair table g_T (67MB) stays L2-resident.
//  prep_all (one launch): pack_T | init_F | thresholds+misc
//    pack: T[s][t'][t] = J[idx(t')][idx(t)] for in-segment step pairs,
//          coalesced stores (thread-strided), smem-gathered.
//  seq_seg(s): single CTA, 544 thr. 512 G-keepers hold G[t]=F[idx(t)] for the
//    1024 segment steps (float2/thread); per flip add d*T[t'][t] for future
//    steps only (~2KB/flip avg, L2). Evaluator warp: R10/R12 ballot machine
//    (Tw in-window, Tc 1-window catch-up). One __syncthreads per window.
//  fold_flips(s): 8 blocks x 512 thr, g_F += sum d*J[i_k,:] (batch 16).

#define NN      4096
#define NSTEPS  16384
#define W       64
#define SS      1024
#define WPS     (SS / W)        // 16
#define NSEG    (NSTEPS / SS)   // 16
#define TPB     544
#define FULLM   0xffffffffu

__device__ float       g_F[NN];
__device__ float2      g_TI[NSTEPS];
__device__ signed char g_m[NN];
__device__ int         g_fl[NSTEPS];        // per-seg flip records: spin | sign<<30
__device__ int         g_flipCnt[NSEG];
__device__ float       g_T[(size_t)NSEG * SS * SS];   // 67MB (L2-resident)

struct Sm {
    float Tw[2][W * W];     // 32KB
    float Tc[2][W * W];     // 32KB
    float Gpub[2][W];
    int   flist[2][W];      // local step | sign<<30
    int   fcnt[2];
    signed char m[NN];      // 4KB
};
#define SMEM_BYTES ((int)sizeof(Sm))

// ---------------------------------------------------------------------------
// fused prep: pack_T | init_F | thresholds + m init
//   blocks [0, NSEG*SS)            : pack one T row (t' = bid)
//   blocks [NSEG*SS, +NN)          : init_F row
//   blocks [NSEG*SS+NN, +64)       : thresholds (64 x 256 = 16384)
//   blocks [+16)                   : g_m init
// ---------------------------------------------------------------------------
__global__ void prep_all(const float* __restrict__ J,
                         const float* __restrict__ h,
                         const float* __restrict__ m0,
                         const int*   __restrict__ idx,
                         const float* __restrict__ u) {
    const int bid = blockIdx.x;
    if (bid < NSEG * SS) {
        // ---- pack one T row ----
        __shared__ float rowS[NN];      // 16KB
        __shared__ int   ids[SS];       // 4KB
        const int s  = bid / SS;
        const int tp = bid % SS;
        const int rowIdx = idx[bid];
        const float4* __restrict__ Jr =
            reinterpret_cast<const float4*>(J) + (size_t)rowIdx * (NN / 4);
        for (int k = threadIdx.x; k < NN / 4; k += 256)
            reinterpret_cast<float4*>(rowS)[k] = Jr[k];
        for (int k = threadIdx.x; k < SS; k += 256)
            ids[k] = idx[s * SS + k];
        __syncthreads();
        float* __restrict__ dst = g_T + (size_t)s * SS * SS + (size_t)tp * SS;
        #pragma unroll
        for (int e = 0; e < SS / 256; e++)
            dst[threadIdx.x + e * 256] = rowS[ids[threadIdx.x + e * 256]];
    } else if (bid < NSEG * SS + NN) {
        // ---- init_F row ----
        const int row = bid - NSEG * SS;
        const float4* __restrict__ Jr =
            reinterpret_cast<const float4*>(J) + (size_t)row * (NN / 4);
        const float4* __restrict__ M4 = reinterpret_cast<const float4*>(m0);
        float sum = 0.0f;
        for (int k = threadIdx.x; k < NN / 4; k += 256) {
            float4 a = Jr[k];
            float4 b = M4[k];
            sum += a.x * b.x + a.y * b.y + a.z * b.z + a.w * b.w;
        }
        #pragma unroll
        for (int off = 16; off; off >>= 1)
            sum += __shfl_xor_sync(FULLM, sum, off);
        __shared__ float ws[8];
        const int lane = threadIdx.x & 31;
        const int wid  = threadIdx.x >> 5;
        if (lane == 0) ws[wid] = sum;
        __syncthreads();
        if (threadIdx.x == 0) {
            float tot = 0.0f;
            #pragma unroll
            for (int w = 0; w < 8; w++) tot += ws[w];
            g_F[row] = tot + h[row];
        }
    } else if (bid < NSEG * SS + NN + 64) {
        const int t = (bid - NSEG * SS - NN) * 256 + threadIdx.x;
        const float r = 2.0f * u[t] - 1.0f;
        g_TI[t] = make_float2(atanhf(r), __int_as_float(idx[t]));
    } else {
        const int k = (bid - NSEG * SS - NN - 64) * 256 + threadIdx.x;
        g_m[k] = (m0[k] > 0.0f) ? 1 : -1;
    }
}

// ---------------------------------------------------------------------------
__global__ __launch_bounds__(512, 1)
void fold_flips(const float* __restrict__ J, int s) {
    const int col = blockIdx.x * 512 + threadIdx.x;   // 8 x 512 = 4096
    const int n = g_flipCnt[s];
    const int* __restrict__ fl = g_fl + s * SS;
    float f = g_F[col];
    int k = 0;
    for (; k + 16 <= n; k += 16) {
        float v[16], d[16];
        #pragma unroll
        for (int j = 0; j < 16; j++) {
            const int e = fl[k + j];
            d[j] = (e & (1 << 30)) ? 2.0f : -2.0f;
            v[j] = __ldg(J + (size_t)(e & 0xFFFF) * NN + col);
        }
        #pragma unroll
        for (int j = 0; j < 16; j++)
            f = fmaf(v[j], d[j], f);
    }
    for (; k < n; k++) {
        const int e = fl[k];
        const float d = (e & (1 << 30)) ? 2.0f : -2.0f;
        f = fmaf(__ldg(J + (size_t)(e & 0xFFFF) * NN + col), d, f);
    }
    g_F[col] = f;
}

// ---------------------------------------------------------------------------
__global__ __launch_bounds__(TPB, 1)
void seq_seg(float* __restrict__ out, int s) {
    extern __shared__ char raw[];
    Sm* S = reinterpret_cast<Sm*>(raw);

    const int tid  = threadIdx.x;
    const int lane = tid & 31;
    const bool is_ev = (tid < 32);
    const int kid   = tid - 32;            // keeper id [0,512)
    const int tbase = 2 * kid;             // owned local steps tbase, tbase+1
    const int segBase = s * SS;
    const float* __restrict__ Tseg = g_T + (size_t)s * SS * SS;

    for (int k = tid; k < NN; k += TPB)
        S->m[k] = g_m[k];
    if (tid == 0) { S->fcnt[0] = 0; S->fcnt[1] = 0; }

    float2 Greg = make_float2(0.f, 0.f);
    float2 tiPF0 = make_float2(0.f, 0.f), tiPF1 = tiPF0;
    unsigned prevM0 = 0, prevS0 = 0, prevM1 = 0, prevS1 = 0;
    int gtot = 0;

    if (is_ev) {
        tiPF0 = g_TI[segBase + lane];
        tiPF1 = g_TI[segBase + 32 + lane];
    } else {
        // G init from g_F at the 2 owned step indices
        const float2 a = g_TI[segBase + tbase];
        const float2 b = g_TI[segBase + tbase + 1];
        Greg.x = g_F[__float_as_int(a.y)];
        Greg.y = g_F[__float_as_int(b.y)];
        // stage Tw[0] (window 0 x window 0)
        const int krow  = kid >> 3;
        const int lbase = (kid & 7) * 8;
        const float* wsrc = Tseg + (size_t)krow * SS + lbase;
        float4 wa = *reinterpret_cast<const float4*>(wsrc);
        float4 wb = *reinterpret_cast<const float4*>(wsrc + 4);
        *reinterpret_cast<float4*>(&S->Tw[0][krow * W + lbase])     = wa;
        *reinterpret_cast<float4*>(&S->Tw[0][krow * W + lbase + 4]) = wb;
        if (kid < 32)
            *reinterpret_cast<float2*>(&S->Gpub[0][tbase]) = Greg;
    }
    __syncthreads();

    for (int p = 0; p < WPS; p++) {
        const int par = p & 1;
        if (is_ev) {
            // ================= evaluator =================
            const float thr0 = tiPF0.x;
            const int   i0   = __float_as_int(tiPF0.y);
            const float thr1 = tiPF1.x;
            const int   i1x  = __float_as_int(tiPF1.y);
            float f0  = S->Gpub[par][lane];
            float f1v = S->Gpub[par][32 + lane];
            bool pos0 = (S->m[i0]  > 0);
            bool pos1 = (S->m[i1x] > 0);
            if (p + 1 < WPS) {
                tiPF0 = g_TI[segBase + (p + 1) * W + lane];
                tiPF1 = g_TI[segBase + (p + 1) * W + 32 + lane];
            }

            // catch up window p-1's flips
            const float* TcP = S->Tc[par];
            {
                unsigned mm = prevM0;
                while (mm) {
                    const int k = __ffs(mm) - 1;
                    mm &= mm - 1;
                    const float dk = ((prevS0 >> k) & 1u) ? 2.0f : -2.0f;
                    f0  = fmaf(TcP[(k << 6) + lane],      dk, f0);
                    f1v = fmaf(TcP[(k << 6) + 32 + lane], dk, f1v);
                }
                mm = prevM1;
                while (mm) {
                    const int k = __ffs(mm) - 1;
                    mm &= mm - 1;
                    const int r = 32 + k;
                    const float dk = ((prevS1 >> k) & 1u) ? 2.0f : -2.0f;
                    f0  = fmaf(TcP[(r << 6) + lane],      dk, f0);
                    f1v = fmaf(TcP[(r << 6) + 32 + lane], dk, f1v);
                }
            }

            const float* TwP = S->Tw[par];
            unsigned nM0 = 0, nS0 = 0, nM1 = 0, nS1 = 0;
            int cnt = 0;

            // half A (steps 0..31)
            {
                bool sp = (f0 >= thr0);
                bool fl = sp != pos0;
                unsigned fb  = __ballot_sync(FULLM, fl);
                unsigned sbm = __ballot_sync(FULLM, sp);
                while (fb) {
                    const int  f = __ffs(fb) - 1;
                    const bool s1 = (sbm >> f) & 1u;
                    const float d = s1 ? 2.0f : -2.0f;
                    const float jva = TwP[(f << 6) + lane];
                    const float jvb = TwP[(f << 6) + 32 + lane];
                    const int   ii  = __shfl_sync(FULLM, i0, f);
                    if (lane == f) {
                        S->m[ii] = s1 ? 1 : -1;
                        const int sg = s1 ? (1 << 30) : 0;
                        S->flist[par][cnt] = (p * W + f) | sg;
                        g_fl[segBase + gtot + cnt] = ii | sg;
                    }
                    nM0 |= 1u << f;
                    if (s1) nS0 |= 1u << f;
                    cnt++;
                    f0  = fmaf(jva, d, f0);
                    f1v = fmaf(jvb, d, f1v);
                    if (i0  == ii) pos0 = s1;
                    if (i1x == ii) pos1 = s1;
                    bool ns = false, nf2 = false;
                    if (lane > f) {
                        ns  = (f0 >= thr0);
                        nf2 = ns != pos0;
                    }
                    fb  = __ballot_sync(FULLM, nf2);
                    sbm = __ballot_sync(FULLM, ns);
                }
            }
            // half B (steps 32..63)
            {
                bool sp = (f1v >= thr1);
                bool fl = sp != pos1;
                unsigned fb  = __ballot_sync(FULLM, fl);
                unsigned sbm = __ballot_sync(FULLM, sp);
                while (fb) {
                    const int  f = __ffs(fb) - 1;
                    const bool s1 = (sbm >> f) & 1u;
                    const float d = s1 ? 2.0f : -2.0f;
                    const int  r = 32 + f;
                    const float jvb = TwP[(r << 6) + 32 + lane];
                    const int   ii  = __shfl_sync(FULLM, i1x, f);
                    if (lane == f) {
                        S->m[ii] = s1 ? 1 : -1;
                        const int sg = s1 ? (1 << 30) : 0;
                        S->flist[par][cnt] = (p * W + 32 + f) | sg;
                        g_fl[segBase + gtot + cnt] = ii | sg;
                    }
                    nM1 |= 1u << f;
                    if (s1) nS1 |= 1u << f;
                    cnt++;
                    f1v = fmaf(jvb, d, f1v);
                    if (i1x == ii) pos1 = s1;
                    bool ns = false, nf2 = false;
                    if (lane > f) {
                        ns  = (f1v >= thr1);
                        nf2 = ns != pos1;
                    }
                    fb  = __ballot_sync(FULLM, nf2);
                    sbm = __ballot_sync(FULLM, ns);
                }
            }
            if (lane == 0) S->fcnt[par] = cnt;
            gtot += cnt;
            prevM0 = nM0; prevS0 = nS0;
            prevM1 = nM1; prevS1 = nS1;
        } else {
            // ================= keepers =================
            const bool hasNext = (p + 1 < WPS);
            const int krow  = kid >> 3;
            const int lbase = (kid & 7) * 8;
            float4 wa, wb, ca, cb;
            if (hasNext) {   // stage tables for window p+1 (LDGs issued early)
                const float* wsrc =
                    Tseg + (size_t)((p + 1) * W + krow) * SS + (p + 1) * W + lbase;
                const float* csrc =
                    Tseg + (size_t)(p * W + krow) * SS + (p + 1) * W + lbase;
                wa = *reinterpret_cast<const float4*>(wsrc);
                wb = *reinterpret_cast<const float4*>(wsrc + 4);
                ca = *reinterpret_cast<const float4*>(csrc);
                cb = *reinterpret_cast<const float4*>(csrc + 4);
            }

            // apply window p-1's flips to future-owned G (batch 8)
            const int np = S->fcnt[par ^ 1];
            const int* fl = S->flist[par ^ 1];
            const bool active = (tbase >= (p + 1) * W);
            for (int kb = 0; kb < np; kb += 8) {
                float  dd[8];
                float2 v[8];
                #pragma unroll
                for (int j = 0; j < 8; j++) {
                    const bool vld = (kb + j < np);
                    const int e = vld ? fl[kb + j] : 0;
                    dd[j] = vld ? ((e & (1 << 30)) ? 2.0f : -2.0f) : 0.0f;
                    const int tp2 = e & 0xFFFF;
                    v[j] = (vld && active)
                        ? *reinterpret_cast<const float2*>(Tseg + (size_t)tp2 * SS + tbase)
                        : make_float2(0.f, 0.f);
                }
                #pragma unroll
                for (int j = 0; j < 8; j++) {
                    Greg.x = fmaf(v[j].x, dd[j], Greg.x);
                    Greg.y = fmaf(v[j].y, dd[j], Greg.y);
                }
            }

            if (hasNext) {
                *reinterpret_cast<float4*>(&S->Tw[par ^ 1][krow * W + lbase])     = wa;
                *reinterpret_cast<float4*>(&S->Tw[par ^ 1][krow * W + lbase + 4]) = wb;
                *reinterpret_cast<float4*>(&S->Tc[par ^ 1][krow * W + lbase])     = ca;
                *reinterpret_cast<float4*>(&S->Tc[par ^ 1][krow * W + lbase + 4]) = cb;
                if ((kid >> 5) == (p + 1))     // publish G for window p+1
                    *reinterpret_cast<float2*>(&S->Gpub[par ^ 1][tbase - (p + 1) * W]) = Greg;
            }
        }
        __syncthreads();
    }

    // ---- epilogue ----
    for (int k = tid; k < NN; k += TPB)
        g_m[k] = S->m[k];
    if (is_ev && lane == 0)
        g_flipCnt[s] = gtot;
    if (s == NSEG - 1)
        for (int k = tid; k < NN; k += TPB)
            out[k] = (float)S->m[k];
}

// ---------------------------------------------------------------------------
extern "C" void kernel_launch(void* const* d_in, const int* in_sizes, int n_in,
                              void* d_out, int out_size) {
    const float* J  = (const float*)d_in[0];
    const float* h  = (const float*)d_in[1];
    const float* m0 = (const float*)d_in[2];
    const int*   idx= (const int*)  d_in[3];
    const float* u  = (const float*)d_in[4];
    float* out = (float*)d_out;

    static bool attrSet = false;
    if (!attrSet) {
        cudaFuncSetAttribute(seq_seg,
                             cudaFuncAttributeMaxDynamicSharedMemorySize,
                             SMEM_BYTES);
        attrSet = true;
    }

    const int prepBlocks = NSEG * SS + NN + 64 + 16;
    prep_all<<<prepBlocks, 256>>>(J, h, m0, idx, u);
    for (int s = 0; s < NSEG; s++) {
        seq_seg<<<1, TPB, SMEM_BYTES>>>(out, s);
        if (s + 1 < NSEG)
            fold_flips<<<8, 512>>>(J, s);
    }
}